// round 15
// baseline (speedup 1.0000x reference)
#include <cuda_runtime.h>
#include <cuda_fp16.h>
#include <cstdint>

#define MROWS   65536
#define DFEAT   512
#define NEDGES  65536
#define NGRAPH  16
#define GSHIFT  12          // rows per graph = 4096

// ---------------------------------------------------------------------------
// Scratch (__device__ globals; allocation-free)
// ---------------------------------------------------------------------------
__device__ float g_S[MROWS];
__device__ float g_rt[NGRAPH * DFEAT];
__device__ float g_rt2[NGRAPH * DFEAT];
__device__ float g_h1root[NGRAPH * DFEAT];
__device__ __half g_f16[(size_t)MROWS * DFEAT];     // fp16 features
__device__ __half g_a16[(size_t)MROWS * DFEAT];     // activation buffer A
__device__ __half g_b16[(size_t)MROWS * DFEAT];     // activation buffer B
__device__ __half g_w1h[512 * 512];
__device__ __half g_w2h[512 * 512];
__device__ __half g_wlh[512 * 512];
// CSR
__device__ int   g_cnt[MROWS];
__device__ int   g_offs[MROWS + 1];
__device__ int   g_cursor[MROWS];
__device__ int   g_ecol[NEDGES];
__device__ float g_ew[NEDGES];

// ---------------------------------------------------------------------------
// PTX helpers
// ---------------------------------------------------------------------------
__device__ __forceinline__ uint32_t smem_u32(const void* p) {
    return (uint32_t)__cvta_generic_to_shared(p);
}
__device__ __forceinline__ void cp_async16(uint32_t dst, const void* src) {
    asm volatile("cp.async.cg.shared.global [%0], [%1], 16;" :: "r"(dst), "l"(src));
}
__device__ __forceinline__ void cp_commit() {
    asm volatile("cp.async.commit_group;");
}
template<int N>
__device__ __forceinline__ void cp_wait() {
    asm volatile("cp.async.wait_group %0;" :: "n"(N));
}
__device__ __forceinline__ void ldsm_x4(uint32_t& r0, uint32_t& r1,
                                        uint32_t& r2, uint32_t& r3, uint32_t a) {
    asm volatile("ldmatrix.sync.aligned.m8n8.x4.shared.b16 {%0,%1,%2,%3}, [%4];"
                 : "=r"(r0), "=r"(r1), "=r"(r2), "=r"(r3) : "r"(a));
}
__device__ __forceinline__ void mma16816(float* c, const uint32_t* a, const uint32_t* b) {
    asm volatile(
        "mma.sync.aligned.m16n8k16.row.col.f32.f16.f16.f32 "
        "{%0,%1,%2,%3}, {%4,%5,%6,%7}, {%8,%9}, {%0,%1,%2,%3};"
        : "+f"(c[0]), "+f"(c[1]), "+f"(c[2]), "+f"(c[3])
        : "r"(a[0]), "r"(a[1]), "r"(a[2]), "r"(a[3]), "r"(b[0]), "r"(b[1]));
}

// ---------------------------------------------------------------------------
// fp16 quantize-store helpers
// ---------------------------------------------------------------------------
__device__ __forceinline__ void q_store2(__half* p, float2 v) {
    *(__half2*)p = __floats2half2_rn(v.x, v.y);
}
__device__ __forceinline__ void q_store4(__half* p, float4 v) {
    q_store2(p,     make_float2(v.x, v.y));
    q_store2(p + 2, make_float2(v.z, v.w));
}

// ---------------------------------------------------------------------------
// fp16 1-term GEMM:  C = A16 @ B16^T   (fp32 accumulate)
// Warp tile 64x32, CTA 128x128, 256 thr (8 warps: 2M x 4N), 2 CTAs/SM.
// 4-stage k32 pipeline: 2 double-buffers x 2 packed halves per 128B row,
// wait_group<2>, prefetch distance 3, ONE __syncthreads per chunk.
// EPI=3: +bias(col); fp32 root-row store; relu; quant->Oh
// EPI=4: +bias(col)+S[row]*rt[g,col]; relu; quant->Oh
// EPI=2: +rt2[g,col]; leaky_relu; fp32 store -> C
// ---------------------------------------------------------------------------
#define BM2 128
#define BN2 128
#define SM_M (BM2 * 128)                  // 16 KB per matrix buffer
#define SMTOTAL (4 * SM_M + 1024)         // A0,B0,A1,B1 (~65 KB)

template<int EPI>
__global__ void __launch_bounds__(256, 2)
gemm_fp16(const __half* __restrict__ A16, const __half* __restrict__ B16,
          float* __restrict__ C, __half* __restrict__ Oh,
          const float* __restrict__ bias, const float* __restrict__ rt,
          const float* __restrict__ S, const int* __restrict__ root_idx,
          float* __restrict__ h1root)
{
    constexpr int K = 512;
    constexpr int NCH = 16;               // k32 chunks
    extern __shared__ char dsm[];
    uint32_t sb = (smem_u32(dsm) + 1023) & ~1023u;

    const int tid  = threadIdx.x;
    const int lane = tid & 31;
    const int wid  = tid >> 5;            // 0..7
    const int wm   = wid & 1;             // 2 M-warps (64 rows each)
    const int wn   = wid >> 1;            // 4 N-warps (32 cols each)
    const long bm  = (long)blockIdx.y * BM2;
    const long bn  = (long)blockIdx.x * BN2;

    float c[4][4][4];
#pragma unroll
    for (int i = 0; i < 4; i++)
#pragma unroll
        for (int j = 0; j < 4; j++)
#pragma unroll
            for (int q = 0; q < 4; q++) c[i][j][q] = 0.0f;

    const int amat  = lane >> 3;
    const int arow0 = wm * 64 + (amat & 1) * 8 + (lane & 7);
    const int ahalf = amat >> 1;
    const int bg    = lane >> 3;
    const int bhalf = bg & 1;
    const int bn0   = wn * 32 + ((bg >> 1) << 3) + (lane & 7);

    const __half* Ap = A16 + bm * K;
    const __half* Bp = B16 + bn * K;

    auto loads = [&](int ch) {
        int kk = ch << 5;                          // k offset (32 per chunk)
        int cb = (ch & 1) * 4;                     // packed-half column base
        uint32_t As = sb + ((ch >> 1) & 1) * (2 * SM_M);
        uint32_t Bs = As + SM_M;
#pragma unroll
        for (int i = 0; i < 2; i++) {
            int lin = tid * 2 + i;                 // 0..511
            int r = lin >> 2;                      // 0..127
            int u = lin & 3;                       // 0..3
            uint32_t off = r * 128 + (((cb + u) ^ (r & 7)) << 4);
            long g = (long)r * K + kk + u * 8;
            cp_async16(As + off, Ap + g);
            cp_async16(Bs + off, Bp + g);
        }
    };

    loads(0); cp_commit();
    loads(1); cp_commit();
    loads(2); cp_commit();

    for (int ch = 0; ch < NCH; ch++) {
        cp_wait<2>();                              // chunk ch has landed
        __syncthreads();                           // all warps done with ch-1
        if (ch + 3 < NCH) loads(ch + 3);           // stage (ch+3)&3 == (ch-1)&3
        cp_commit();

        int cb = (ch & 1) * 4;
        uint32_t As = sb + ((ch >> 1) & 1) * (2 * SM_M);
        uint32_t Bs = As + SM_M;
#pragma unroll
        for (int t = 0; t < 2; t++) {
            uint32_t a[4][4];
#pragma unroll
            for (int mi = 0; mi < 4; mi++) {
                int row = arow0 + mi * 16;
                uint32_t off = row * 128 + (((cb + 2 * t + ahalf) ^ (row & 7)) << 4);
                ldsm_x4(a[mi][0], a[mi][1], a[mi][2], a[mi][3], As + off);
            }
            uint32_t b[4][2];
#pragma unroll
            for (int j = 0; j < 2; j++) {
                int n = bn0 + j * 16;
                uint32_t off = n * 128 + (((cb + 2 * t + bhalf) ^ (n & 7)) << 4);
                ldsm_x4(b[2 * j][0], b[2 * j][1], b[2 * j + 1][0], b[2 * j + 1][1], Bs + off);
            }
#pragma unroll
            for (int mi = 0; mi < 4; mi++)
#pragma unroll
                for (int nj = 0; nj < 4; nj++)
                    mma16816(c[mi][nj], a[mi], b[nj]);
        }
    }

#pragma unroll
    for (int mi = 0; mi < 4; mi++) {
        long row = bm + wm * 64 + mi * 16 + (lane >> 2);
        int g = (int)(row >> GSHIFT);
#pragma unroll
        for (int nj = 0; nj < 4; nj++) {
            int col = (int)bn + wn * 32 + nj * 8 + 2 * (lane & 3);
            float2 v0 = {c[mi][nj][0], c[mi][nj][1]};   // row
            float2 v1 = {c[mi][nj][2], c[mi][nj][3]};   // row + 8

            if (EPI == 3) {
                float b0 = bias[col], b1v = bias[col + 1];
                v0.x += b0; v0.y += b1v; v1.x += b0; v1.y += b1v;
                int rr = root_idx[g];
                if ((long)rr == row) {
                    h1root[g * 512 + col] = v0.x; h1root[g * 512 + col + 1] = v0.y;
                }
                if ((long)rr == row + 8) {
                    h1root[g * 512 + col] = v1.x; h1root[g * 512 + col + 1] = v1.y;
                }
                v0.x = fmaxf(v0.x, 0.f); v0.y = fmaxf(v0.y, 0.f);
                v1.x = fmaxf(v1.x, 0.f); v1.y = fmaxf(v1.y, 0.f);
                q_store2(Oh + row * 512 + col, v0);
                q_store2(Oh + (row + 8) * 512 + col, v1);
            } else if (EPI == 4) {
                float s0 = S[row], s1 = S[row + 8];
                float r0 = rt[g * 512 + col], r1 = rt[g * 512 + col + 1];
                float b0 = bias[col], b1v = bias[col + 1];
                v0.x += b0 + s0 * r0; v0.y += b1v + s0 * r1;
                v1.x += b0 + s1 * r0; v1.y += b1v + s1 * r1;
                v0.x = fmaxf(v0.x, 0.f); v0.y = fmaxf(v0.y, 0.f);
                v1.x = fmaxf(v1.x, 0.f); v1.y = fmaxf(v1.y, 0.f);
                q_store2(Oh + row * 512 + col, v0);
                q_store2(Oh + (row + 8) * 512 + col, v1);
            } else {  // EPI == 2
                float b0 = rt[g * 512 + col], b1v = rt[g * 512 + col + 1];
                v0.x += b0; v0.y += b1v; v1.x += b0; v1.y += b1v;
                v0.x = (v0.x >= 0.f) ? v0.x : 0.01f * v0.x;
                v0.y = (v0.y >= 0.f) ? v0.y : 0.01f * v0.y;
                v1.x = (v1.x >= 0.f) ? v1.x : 0.01f * v1.x;
                v1.y = (v1.y >= 0.f) ? v1.y : 0.01f * v1.y;
                *(float2*)(C + row * 512 + col)       = v0;
                *(float2*)(C + (row + 8) * 512 + col) = v1;
            }
        }
    }
}

// ---------------------------------------------------------------------------
// prep: convert weights + features to fp16, zero cnt/S, init rt/rt2
// ---------------------------------------------------------------------------
__global__ void prep_kernel(const float* __restrict__ feat,
                            const float* __restrict__ W1,
                            const float* __restrict__ W2,
                            const float* __restrict__ Wl,
                            const float* __restrict__ bl,
                            __half* __restrict__ f16,
                            __half* __restrict__ w1h,
                            __half* __restrict__ w2h,
                            __half* __restrict__ wlh,
                            int* __restrict__ cnt, float* __restrict__ S,
                            float* __restrict__ rt, float* __restrict__ rt2)
{
    long idx = (long)blockIdx.x * blockDim.x + threadIdx.x;
    if (idx < MROWS) { cnt[idx] = 0; S[idx] = 0.f; }
    if (idx < NGRAPH * DFEAT) { rt[idx] = 0.f; rt2[idx] = bl[idx & 511]; }
    if (idx < 3 * 512 * 512) {
        int which = (int)(idx >> 18);
        int loc   = (int)(idx & 0x3FFFF);
        int n = loc >> 9;
        int k = loc & 511;
        const float* W = (which == 0) ? W1 : (which == 1) ? W2 : Wl;
        __half* wh = (which == 0) ? w1h : (which == 1) ? w2h : wlh;
        wh[loc] = __float2half_rn(__ldg(&W[(long)k * 512 + n]));
    }
    if (idx < (long)MROWS * 128) {
        float4 v = ((const float4*)feat)[idx];
        q_store4(f16 + idx * 4, v);
    }
}

// ---------------------------------------------------------------------------
// CSR build: hist (+S row sums), then fused scan+fill (single block)
// ---------------------------------------------------------------------------
__global__ void hist_kernel(const int* __restrict__ rows,
                            const float* __restrict__ vals,
                            int* __restrict__ cnt, float* __restrict__ S, int nE)
{
    int e = blockIdx.x * blockDim.x + threadIdx.x;
    if (e < nE) {
        atomicAdd(&cnt[rows[e]], 1);
        atomicAdd(&S[rows[e]], vals[e]);
    }
}
__global__ void __launch_bounds__(1024, 1)
scanfill_kernel(const int* __restrict__ cnt, int* __restrict__ offs,
                int* __restrict__ cursor,
                const int* __restrict__ rows, const int* __restrict__ cols,
                const float* __restrict__ vals,
                int* __restrict__ ecol, float* __restrict__ ew, int nE)
{
    __shared__ int ts[1024];
    const int tid = threadIdx.x;
    const int base = tid * 64;
    int local = 0;
#pragma unroll 8
    for (int i = 0; i < 64; i++) local += cnt[base + i];
    int x = local;
    ts[tid] = x; __syncthreads();
    for (int s = 1; s < 1024; s <<= 1) {
        int v = (tid >= s) ? ts[tid - s] : 0;
        __syncthreads();
        x += v; ts[tid] = x; __syncthreads();
    }
    int run = x - local;
    for (int i = 0; i < 64; i++) {
        int cc = cnt[base + i];
        offs[base + i] = run;
        cursor[base + i] = run;
        run += cc;
    }
    if (tid == 1023) offs[MROWS] = run;
    __syncthreads();
    // fill
    for (int e = tid; e < nE; e += 1024) {
        int p = atomicAdd(&cursor[rows[e]], 1);
        ecol[p] = cols[e];
        ew[p]   = vals[e];
    }
}

// ---------------------------------------------------------------------------
// CSR gather (fp16 src -> fp16 dst), one 128-thread block per row
// ---------------------------------------------------------------------------
__device__ __forceinline__ float4 ld_f16row(const __half* sh, long row, int tid)
{
    const __half2* ph = (const __half2*)(sh + row * 512) + tid * 2;
    __half2 h0 = __ldg(ph), h1 = __ldg(ph + 1);
    float4 v;
    v.x = __half2float(h0.x); v.y = __half2float(h0.y);
    v.z = __half2float(h1.x); v.w = __half2float(h1.y);
    return v;
}

__global__ void __launch_bounds__(128)
gather_f16_kernel(const __half* __restrict__ sh,
                  const int* __restrict__ offs, const int* __restrict__ ecol,
                  const float* __restrict__ ew, __half* __restrict__ oh)
{
    const int r = blockIdx.x;
    const int tid = threadIdx.x;
    const int beg = __ldg(&offs[r]), end = __ldg(&offs[r + 1]);
    float4 acc = make_float4(0.f, 0.f, 0.f, 0.f);
    int i = beg;
    for (; i + 4 <= end; i += 4) {
        int c0 = __ldg(&ecol[i]),   c1 = __ldg(&ecol[i+1]);
        int c2 = __ldg(&ecol[i+2]), c3 = __ldg(&ecol[i+3]);
        float w0 = __ldg(&ew[i]),   w1 = __ldg(&ew[i+1]);
        float w2 = __ldg(&ew[i+2]), w3 = __ldg(&ew[i+3]);
        float4 v0 = ld_f16row(sh, c0, tid);
        float4 v1 = ld_f16row(sh, c1, tid);
        float4 v2 = ld_f16row(sh, c2, tid);
        float4 v3 = ld_f16row(sh, c3, tid);
        acc.x += w0*v0.x + w1*v1.x + w2*v2.x + w3*v3.x;
        acc.y += w0*v0.y + w1*v1.y + w2*v2.y + w3*v3.y;
        acc.z += w0*v0.z + w1*v1.z + w2*v2.z + w3*v3.z;
        acc.w += w0*v0.w + w1*v1.w + w2*v2.w + w3*v3.w;
    }
    for (; i < end; i++) {
        int cc = __ldg(&ecol[i]);
        float w = __ldg(&ew[i]);
        float4 v = ld_f16row(sh, cc, tid);
        acc.x += w * v.x; acc.y += w * v.y; acc.z += w * v.z; acc.w += w * v.w;
    }
    q_store4(oh + (long)r * 512 + tid * 4, acc);
}

// ---------------------------------------------------------------------------
// root terms (fp32 exact)
// ---------------------------------------------------------------------------
__global__ void __launch_bounds__(512)
root_term_kernel(const float* __restrict__ feat, const int* __restrict__ root_idx,
                 const float* __restrict__ W2, float* __restrict__ rt)
{
    int g  = blockIdx.x;
    int kc = blockIdx.y << 6;
    int n  = threadIdx.x;
    const float* v  = feat + (long)root_idx[g] * DFEAT + kc;
    const float* Wb = W2 + (long)(512 + kc) * 512 + n;
    float acc = 0.f;
#pragma unroll 8
    for (int k = 0; k < 64; k++)
        acc += fmaxf(__ldg(v + k), 0.f) * __ldg(Wb + (long)k * 512);
    atomicAdd(&rt[g * DFEAT + n], acc);
}
__global__ void __launch_bounds__(512)
root_term2_kernel(const float* __restrict__ h1root, const float* __restrict__ Wl,
                  float* __restrict__ rt2)
{
    int g  = blockIdx.x;
    int kc = blockIdx.y << 6;
    int n  = threadIdx.x;
    const float* v  = h1root + g * DFEAT + kc;
    const float* Wb = Wl + (long)(512 + kc) * 512 + n;
    float acc = 0.f;
#pragma unroll 8
    for (int k = 0; k < 64; k++)
        acc += __ldg(v + k) * __ldg(Wb + (long)k * 512);
    atomicAdd(&rt2[g * DFEAT + n], acc);
}

// ---------------------------------------------------------------------------
// launch  (index 3 == gather_f16 -> ncu target next round)
// ---------------------------------------------------------------------------
extern "C" void kernel_launch(void* const* d_in, const int* in_sizes, int n_in,
                              void* d_out, int out_size)
{
    const float* features = (const float*)d_in[0];
    const int*   adjs     = (const int*)  d_in[1];
    const float* values   = (const float*)d_in[2];
    const int*   root_idx = (const int*)  d_in[3];
    const float* W1 = (const float*)d_in[6];
    const float* b1 = (const float*)d_in[7];
    const float* W2 = (const float*)d_in[8];
    const float* b2 = (const float*)d_in[9];
    const float* Wl = (const float*)d_in[10];
    const float* bl = (const float*)d_in[11];
    float* out = (float*)d_out;

    const int nE = in_sizes[2];

    float *S, *rt, *rt2, *h1root, *ew;
    int *cnt, *offs, *cursor, *ecol;
    __half *f16, *a16, *b16, *w1h, *w2h, *wlh;
    cudaGetSymbolAddress((void**)&S,      g_S);
    cudaGetSymbolAddress((void**)&rt,     g_rt);
    cudaGetSymbolAddress((void**)&rt2,    g_rt2);
    cudaGetSymbolAddress((void**)&h1root, g_h1root);
    cudaGetSymbolAddress((void**)&cnt,    g_cnt);
    cudaGetSymbolAddress((void**)&offs,   g_offs);
    cudaGetSymbolAddress((void**)&cursor, g_cursor);
    cudaGetSymbolAddress((void**)&ecol,   g_ecol);
    cudaGetSymbolAddress((void**)&ew,     g_ew);
    cudaGetSymbolAddress((void**)&f16, g_f16);
    cudaGetSymbolAddress((void**)&a16, g_a16);
    cudaGetSymbolAddress((void**)&b16, g_b16);
    cudaGetSymbolAddress((void**)&w1h, g_w1h);
    cudaGetSymbolAddress((void**)&w2h, g_w2h);
    cudaGetSymbolAddress((void**)&wlh, g_wlh);

    const int* rows = adjs;
    const int* cols = adjs + nE;

    cudaFuncSetAttribute(gemm_fp16<3>, cudaFuncAttributeMaxDynamicSharedMemorySize, SMTOTAL);
    cudaFuncSetAttribute(gemm_fp16<4>, cudaFuncAttributeMaxDynamicSharedMemorySize, SMTOTAL);
    cudaFuncSetAttribute(gemm_fp16<2>, cudaFuncAttributeMaxDynamicSharedMemorySize, SMTOTAL);

    dim3 ggrid(DFEAT / BN2, MROWS / BM2);             // (4, 512)
    dim3 rtg(NGRAPH, 8);

    // #0: prep (weights+features -> fp16, zero cnt/S, init rt/rt2)
    prep_kernel<<<(int)(((long)MROWS * 128 + 255) / 256), 256>>>(
        features, W1, W2, Wl, bl, f16, w1h, w2h, wlh, cnt, S, rt, rt2);
    // #1: hist + S row sums
    hist_kernel<<<(nE + 255) / 256, 256>>>(rows, values, cnt, S, nE);
    // #2: fused scan + fill
    scanfill_kernel<<<1, 1024>>>(cnt, offs, cursor, rows, cols, values, ecol, ew, nE);
    // #3: PX = P @ X (fp16)                               <-- ncu target
    gather_f16_kernel<<<MROWS, 128>>>(f16, offs, ecol, ew, a16);
    // #4: h1 = PX @ W1 + b1 (root-store, relu, quant) -> b16
    gemm_fp16<3><<<ggrid, 256, SMTOTAL>>>(a16, w1h, nullptr, b16,
                                          b1, nullptr, nullptr, root_idx, h1root);
    // #5-6: root terms
    root_term_kernel<<<rtg, 512>>>(features, root_idx, W2, rt);
    root_term2_kernel<<<rtg, 512>>>(h1root, Wl, rt2);
    // #7: Y = P @ relu(h1) (fp16) -> a16
    gather_f16_kernel<<<MROWS, 128>>>(b16, offs, ecol, ew, a16);
    // #8: h2 = Y @ W2a + b2 + S*rt[g] (relu, quant) -> b16
    gemm_fp16<4><<<ggrid, 256, SMTOTAL>>>(a16, w2h, nullptr, b16,
                                          b2, rt, S, nullptr, nullptr);
    // #9: out = leaky_relu(relu(h2) @ Wla + rt2[g])
    gemm_fp16<2><<<ggrid, 256, SMTOTAL>>>(b16, wlh, out, nullptr,
                                          nullptr, rt2, nullptr, nullptr, nullptr);
}

// round 16
// speedup vs baseline: 1.1617x; 1.1617x over previous
#include <cuda_runtime.h>
#include <cuda_fp16.h>
#include <cstdint>

#define MROWS   65536
#define DFEAT   512
#define NEDGES  65536
#define NGRAPH  16
#define GSHIFT  12          // rows per graph = 4096

// ---------------------------------------------------------------------------
// Scratch (__device__ globals; allocation-free)
// ---------------------------------------------------------------------------
__device__ float g_S[MROWS];
__device__ float g_rt[NGRAPH * DFEAT];
__device__ float g_rt2[NGRAPH * DFEAT];
__device__ float g_h1root[NGRAPH * DFEAT];
__device__ __half g_a16[(size_t)MROWS * DFEAT];     // activation buffer A
__device__ __half g_b16[(size_t)MROWS * DFEAT];     // activation buffer B
__device__ __half g_w1h[512 * 512];
__device__ __half g_w2h[512 * 512];
__device__ __half g_wlh[512 * 512];
// CSR
__device__ int   g_cnt[MROWS];
__device__ int   g_offs[MROWS + 1];
__device__ int   g_cursor[MROWS];
__device__ int   g_ecol[NEDGES];
__device__ float g_ew[NEDGES];

// ---------------------------------------------------------------------------
// PTX helpers
// ---------------------------------------------------------------------------
__device__ __forceinline__ uint32_t smem_u32(const void* p) {
    return (uint32_t)__cvta_generic_to_shared(p);
}
__device__ __forceinline__ void cp_async16(uint32_t dst, const void* src) {
    asm volatile("cp.async.cg.shared.global [%0], [%1], 16;" :: "r"(dst), "l"(src));
}
__device__ __forceinline__ void cp_commit() {
    asm volatile("cp.async.commit_group;");
}
template<int N>
__device__ __forceinline__ void cp_wait() {
    asm volatile("cp.async.wait_group %0;" :: "n"(N));
}
__device__ __forceinline__ void ldsm_x4(uint32_t& r0, uint32_t& r1,
                                        uint32_t& r2, uint32_t& r3, uint32_t a) {
    asm volatile("ldmatrix.sync.aligned.m8n8.x4.shared.b16 {%0,%1,%2,%3}, [%4];"
                 : "=r"(r0), "=r"(r1), "=r"(r2), "=r"(r3) : "r"(a));
}
__device__ __forceinline__ void mma16816(float* c, const uint32_t* a, const uint32_t* b) {
    asm volatile(
        "mma.sync.aligned.m16n8k16.row.col.f32.f16.f16.f32 "
        "{%0,%1,%2,%3}, {%4,%5,%6,%7}, {%8,%9}, {%0,%1,%2,%3};"
        : "+f"(c[0]), "+f"(c[1]), "+f"(c[2]), "+f"(c[3])
        : "r"(a[0]), "r"(a[1]), "r"(a[2]), "r"(a[3]), "r"(b[0]), "r"(b[1]));
}

// ---------------------------------------------------------------------------
// fp16 quantize-store helpers
// ---------------------------------------------------------------------------
__device__ __forceinline__ void q_store2(__half* p, float2 v) {
    *(__half2*)p = __floats2half2_rn(v.x, v.y);
}
__device__ __forceinline__ void q_store4(__half* p, float4 v) {
    q_store2(p,     make_float2(v.x, v.y));
    q_store2(p + 2, make_float2(v.z, v.w));
}

// ---------------------------------------------------------------------------
// fp16 1-term GEMM:  C = A16 @ B16^T   (fp32 accumulate)
// Warp tile 64x32, CTA 128x128, 256 thr (8 warps: 2M x 4N), 2 CTAs/SM.
// 3-stage k64 ring; loads(ch+2) issued BEFORE compute(ch) (stage disjoint),
// ONE __syncthreads per chunk; 2 chunks always in flight (~2000 cyc lead).
// EPI=3: +bias(col); fp32 root-row store; relu; quant->Oh
// EPI=4: +bias(col)+S[row]*rt[g,col]; relu; quant->Oh
// EPI=2: +rt2[g,col]; leaky_relu; fp32 store -> C
// ---------------------------------------------------------------------------
#define BM2 128
#define BN2 128
#define SM_M (BM2 * 128)                  // 16 KB per matrix buffer
#define SMTOTAL (6 * SM_M + 1024)         // 3 stages x (A,B)  (~97 KB)

template<int EPI>
__global__ void __launch_bounds__(256, 2)
gemm_fp16(const __half* __restrict__ A16, const __half* __restrict__ B16,
          float* __restrict__ C, __half* __restrict__ Oh,
          const float* __restrict__ bias, const float* __restrict__ rt,
          const float* __restrict__ S, const int* __restrict__ root_idx,
          float* __restrict__ h1root)
{
    constexpr int K = 512;
    constexpr int NCH = 8;                // k64 chunks
    extern __shared__ char dsm[];
    uint32_t sb = (smem_u32(dsm) + 1023) & ~1023u;

    const int tid  = threadIdx.x;
    const int lane = tid & 31;
    const int wid  = tid >> 5;            // 0..7
    const int wm   = wid & 1;             // 2 M-warps (64 rows each)
    const int wn   = wid >> 1;            // 4 N-warps (32 cols each)
    const long bm  = (long)blockIdx.y * BM2;
    const long bn  = (long)blockIdx.x * BN2;

    float c[4][4][4];
#pragma unroll
    for (int i = 0; i < 4; i++)
#pragma unroll
        for (int j = 0; j < 4; j++)
#pragma unroll
            for (int q = 0; q < 4; q++) c[i][j][q] = 0.0f;

    const int amat  = lane >> 3;
    const int arow0 = wm * 64 + (amat & 1) * 8 + (lane & 7);
    const int ahalf = amat >> 1;
    const int bg    = lane >> 3;
    const int bhalf = bg & 1;
    const int bn0   = wn * 32 + ((bg >> 1) << 3) + (lane & 7);

    const __half* Ap = A16 + bm * K;
    const __half* Bp = B16 + bn * K;

    auto loads = [&](int ch, int s) {
        int kk = ch << 6;                          // k offset (64 per chunk)
        uint32_t As = sb + s * (2 * SM_M);
        uint32_t Bs = As + SM_M;
#pragma unroll
        for (int i = 0; i < 4; i++) {
            int lin = tid * 4 + i;                 // 0..1023
            int r = lin >> 3;                      // 0..127
            int u = lin & 7;                       // 0..7
            uint32_t off = r * 128 + ((u ^ (r & 7)) << 4);
            long g = (long)r * K + kk + u * 8;
            cp_async16(As + off, Ap + g);
            cp_async16(Bs + off, Bp + g);
        }
    };

    loads(0, 0); cp_commit();
    loads(1, 1); cp_commit();

    int st = 0;                                    // stage of current chunk
    for (int ch = 0; ch < NCH; ch++) {
        cp_wait<1>();                              // chunk ch has landed
        __syncthreads();                           // all warps done with ch-1
        if (ch + 2 < NCH) {
            int ps = st + 2; if (ps >= 3) ps -= 3; // stage (ch+2)%3 == (ch-1)%3
            loads(ch + 2, ps);
        }
        cp_commit();

        uint32_t As = sb + st * (2 * SM_M);
        uint32_t Bs = As + SM_M;
#pragma unroll
        for (int t = 0; t < 4; t++) {
            uint32_t a[4][4];
#pragma unroll
            for (int mi = 0; mi < 4; mi++) {
                int row = arow0 + mi * 16;
                uint32_t off = row * 128 + (((2 * t + ahalf) ^ (row & 7)) << 4);
                ldsm_x4(a[mi][0], a[mi][1], a[mi][2], a[mi][3], As + off);
            }
            uint32_t b[4][2];
#pragma unroll
            for (int j = 0; j < 2; j++) {
                int n = bn0 + j * 16;
                uint32_t off = n * 128 + (((2 * t + bhalf) ^ (n & 7)) << 4);
                ldsm_x4(b[2 * j][0], b[2 * j][1], b[2 * j + 1][0], b[2 * j + 1][1], Bs + off);
            }
#pragma unroll
            for (int mi = 0; mi < 4; mi++)
#pragma unroll
                for (int nj = 0; nj < 4; nj++)
                    mma16816(c[mi][nj], a[mi], b[nj]);
        }
        if (++st == 3) st = 0;
    }

#pragma unroll
    for (int mi = 0; mi < 4; mi++) {
        long row = bm + wm * 64 + mi * 16 + (lane >> 2);
        int g = (int)(row >> GSHIFT);
#pragma unroll
        for (int nj = 0; nj < 4; nj++) {
            int col = (int)bn + wn * 32 + nj * 8 + 2 * (lane & 3);
            float2 v0 = {c[mi][nj][0], c[mi][nj][1]};   // row
            float2 v1 = {c[mi][nj][2], c[mi][nj][3]};   // row + 8

            if (EPI == 3) {
                float b0 = bias[col], b1v = bias[col + 1];
                v0.x += b0; v0.y += b1v; v1.x += b0; v1.y += b1v;
                int rr = root_idx[g];
                if ((long)rr == row) {
                    h1root[g * 512 + col] = v0.x; h1root[g * 512 + col + 1] = v0.y;
                }
                if ((long)rr == row + 8) {
                    h1root[g * 512 + col] = v1.x; h1root[g * 512 + col + 1] = v1.y;
                }
                v0.x = fmaxf(v0.x, 0.f); v0.y = fmaxf(v0.y, 0.f);
                v1.x = fmaxf(v1.x, 0.f); v1.y = fmaxf(v1.y, 0.f);
                q_store2(Oh + row * 512 + col, v0);
                q_store2(Oh + (row + 8) * 512 + col, v1);
            } else if (EPI == 4) {
                float s0 = S[row], s1 = S[row + 8];
                float r0 = rt[g * 512 + col], r1 = rt[g * 512 + col + 1];
                float b0 = bias[col], b1v = bias[col + 1];
                v0.x += b0 + s0 * r0; v0.y += b1v + s0 * r1;
                v1.x += b0 + s1 * r0; v1.y += b1v + s1 * r1;
                v0.x = fmaxf(v0.x, 0.f); v0.y = fmaxf(v0.y, 0.f);
                v1.x = fmaxf(v1.x, 0.f); v1.y = fmaxf(v1.y, 0.f);
                q_store2(Oh + row * 512 + col, v0);
                q_store2(Oh + (row + 8) * 512 + col, v1);
            } else {  // EPI == 2
                float b0 = rt[g * 512 + col], b1v = rt[g * 512 + col + 1];
                v0.x += b0; v0.y += b1v; v1.x += b0; v1.y += b1v;
                v0.x = (v0.x >= 0.f) ? v0.x : 0.01f * v0.x;
                v0.y = (v0.y >= 0.f) ? v0.y : 0.01f * v0.y;
                v1.x = (v1.x >= 0.f) ? v1.x : 0.01f * v1.x;
                v1.y = (v1.y >= 0.f) ? v1.y : 0.01f * v1.y;
                *(float2*)(C + row * 512 + col)       = v0;
                *(float2*)(C + (row + 8) * 512 + col) = v1;
            }
        }
    }
}

// ---------------------------------------------------------------------------
// prep: weights -> fp16 transposed, zero CSR histogram, init rt/rt2
// ---------------------------------------------------------------------------
__global__ void split_w_zero_kernel(const float* __restrict__ W1,
                                    const float* __restrict__ W2,
                                    const float* __restrict__ Wl,
                                    const float* __restrict__ bl,
                                    __half* __restrict__ w1h,
                                    __half* __restrict__ w2h,
                                    __half* __restrict__ wlh,
                                    int* __restrict__ cnt,
                                    float* __restrict__ rt, float* __restrict__ rt2)
{
    long idx = (long)blockIdx.x * blockDim.x + threadIdx.x;
    if (idx < MROWS) cnt[idx] = 0;
    if (idx < NGRAPH * DFEAT) { rt[idx] = 0.f; rt2[idx] = bl[idx & 511]; }
    if (idx >= 3 * 512 * 512) return;
    int which = (int)(idx >> 18);
    int loc   = (int)(idx & 0x3FFFF);
    int n = loc >> 9;
    int k = loc & 511;
    const float* W = (which == 0) ? W1 : (which == 1) ? W2 : Wl;
    __half* wh = (which == 0) ? w1h : (which == 1) ? w2h : wlh;
    wh[loc] = __float2half_rn(__ldg(&W[(long)k * 512 + n]));
}

// ---------------------------------------------------------------------------
// CSR build
// ---------------------------------------------------------------------------
__global__ void hist_kernel(const int* __restrict__ rows, int* __restrict__ cnt, int nE)
{
    int e = blockIdx.x * blockDim.x + threadIdx.x;
    if (e < nE) atomicAdd(&cnt[rows[e]], 1);
}
__global__ void __launch_bounds__(1024, 1)
scan_kernel(const int* __restrict__ cnt, int* __restrict__ offs, int* __restrict__ cursor)
{
    __shared__ int ts[1024];
    const int tid = threadIdx.x;
    const int base = tid * 64;
    int local = 0;
#pragma unroll 8
    for (int i = 0; i < 64; i++) local += cnt[base + i];
    int x = local;
    ts[tid] = x; __syncthreads();
    for (int s = 1; s < 1024; s <<= 1) {
        int v = (tid >= s) ? ts[tid - s] : 0;
        __syncthreads();
        x += v; ts[tid] = x; __syncthreads();
    }
    int run = x - local;
    for (int i = 0; i < 64; i++) {
        int cc = cnt[base + i];
        offs[base + i] = run;
        cursor[base + i] = run;
        run += cc;
    }
    if (tid == 1023) offs[MROWS] = run;
}
__global__ void fill_csr_kernel(const int* __restrict__ rows, const int* __restrict__ cols,
                                const float* __restrict__ vals, int* __restrict__ cursor,
                                int* __restrict__ ecol, float* __restrict__ ew, int nE)
{
    int e = blockIdx.x * blockDim.x + threadIdx.x;
    if (e >= nE) return;
    int p = atomicAdd(&cursor[rows[e]], 1);
    ecol[p] = cols[e];
    ew[p]   = vals[e];
}

// ---------------------------------------------------------------------------
// CSR gathers (one 128-thread block per destination row), 4-edge batching
// ---------------------------------------------------------------------------
__global__ void __launch_bounds__(128)
gather_f32_kernel(const float* __restrict__ src, const int* __restrict__ offs,
                  const int* __restrict__ ecol, const float* __restrict__ ew,
                  __half* __restrict__ oh, float* __restrict__ S)
{
    const int r = blockIdx.x;
    const int tid = threadIdx.x;
    const int beg = __ldg(&offs[r]), end = __ldg(&offs[r + 1]);
    float4 acc = make_float4(0.f, 0.f, 0.f, 0.f);
    float s = 0.f;
    int i = beg;
    for (; i + 4 <= end; i += 4) {
        int c0 = __ldg(&ecol[i]),   c1 = __ldg(&ecol[i+1]);
        int c2 = __ldg(&ecol[i+2]), c3 = __ldg(&ecol[i+3]);
        float w0 = __ldg(&ew[i]),   w1 = __ldg(&ew[i+1]);
        float w2 = __ldg(&ew[i+2]), w3 = __ldg(&ew[i+3]);
        float4 v0 = __ldg((const float4*)(src + (long)c0 * 512) + tid);
        float4 v1 = __ldg((const float4*)(src + (long)c1 * 512) + tid);
        float4 v2 = __ldg((const float4*)(src + (long)c2 * 512) + tid);
        float4 v3 = __ldg((const float4*)(src + (long)c3 * 512) + tid);
        acc.x += w0*v0.x + w1*v1.x + w2*v2.x + w3*v3.x;
        acc.y += w0*v0.y + w1*v1.y + w2*v2.y + w3*v3.y;
        acc.z += w0*v0.z + w1*v1.z + w2*v2.z + w3*v3.z;
        acc.w += w0*v0.w + w1*v1.w + w2*v2.w + w3*v3.w;
        s += w0 + w1 + w2 + w3;
    }
    for (; i < end; i++) {
        int cc = __ldg(&ecol[i]);
        float w = __ldg(&ew[i]);
        float4 v = __ldg((const float4*)(src + (long)cc * 512) + tid);
        acc.x += w * v.x; acc.y += w * v.y; acc.z += w * v.z; acc.w += w * v.w;
        s += w;
    }
    if (tid == 0) S[r] = s;
    q_store4(oh + (long)r * 512 + tid * 4, acc);
}

__device__ __forceinline__ float4 ld_f16row(const __half* sh, long row, int tid)
{
    const __half2* ph = (const __half2*)(sh + row * 512) + tid * 2;
    __half2 h0 = __ldg(ph), h1 = __ldg(ph + 1);
    float4 v;
    v.x = __half2float(h0.x); v.y = __half2float(h0.y);
    v.z = __half2float(h1.x); v.w = __half2float(h1.y);
    return v;
}

__global__ void __launch_bounds__(128)
gather_f16_kernel(const __half* __restrict__ sh,
                  const int* __restrict__ offs, const int* __restrict__ ecol,
                  const float* __restrict__ ew, __half* __restrict__ oh)
{
    const int r = blockIdx.x;
    const int tid = threadIdx.x;
    const int beg = __ldg(&offs[r]), end = __ldg(&offs[r + 1]);
    float4 acc = make_float4(0.f, 0.f, 0.f, 0.f);
    int i = beg;
    for (; i + 4 <= end; i += 4) {
        int c0 = __ldg(&ecol[i]),   c1 = __ldg(&ecol[i+1]);
        int c2 = __ldg(&ecol[i+2]), c3 = __ldg(&ecol[i+3]);
        float w0 = __ldg(&ew[i]),   w1 = __ldg(&ew[i+1]);
        float w2 = __ldg(&ew[i+2]), w3 = __ldg(&ew[i+3]);
        float4 v0 = ld_f16row(sh, c0, tid);
        float4 v1 = ld_f16row(sh, c1, tid);
        float4 v2 = ld_f16row(sh, c2, tid);
        float4 v3 = ld_f16row(sh, c3, tid);
        acc.x += w0*v0.x + w1*v1.x + w2*v2.x + w3*v3.x;
        acc.y += w0*v0.y + w1*v1.y + w2*v2.y + w3*v3.y;
        acc.z += w0*v0.z + w1*v1.z + w2*v2.z + w3*v3.z;
        acc.w += w0*v0.w + w1*v1.w + w2*v2.w + w3*v3.w;
    }
    for (; i < end; i++) {
        int cc = __ldg(&ecol[i]);
        float w = __ldg(&ew[i]);
        float4 v = ld_f16row(sh, cc, tid);
        acc.x += w * v.x; acc.y += w * v.y; acc.z += w * v.z; acc.w += w * v.w;
    }
    q_store4(oh + (long)r * 512 + tid * 4, acc);
}

// ---------------------------------------------------------------------------
// root terms (fp32 exact)
// ---------------------------------------------------------------------------
__global__ void __launch_bounds__(512)
root_term_kernel(const float* __restrict__ feat, const int* __restrict__ root_idx,
                 const float* __restrict__ W2, float* __restrict__ rt)
{
    int g  = blockIdx.x;
    int kc = blockIdx.y << 6;
    int n  = threadIdx.x;
    const float* v  = feat + (long)root_idx[g] * DFEAT + kc;
    const float* Wb = W2 + (long)(512 + kc) * 512 + n;
    float acc = 0.f;
#pragma unroll 8
    for (int k = 0; k < 64; k++)
        acc += fmaxf(__ldg(v + k), 0.f) * __ldg(Wb + (long)k * 512);
    atomicAdd(&rt[g * DFEAT + n], acc);
}
__global__ void __launch_bounds__(512)
root_term2_kernel(const float* __restrict__ h1root, const float* __restrict__ Wl,
                  float* __restrict__ rt2)
{
    int g  = blockIdx.x;
    int kc = blockIdx.y << 6;
    int n  = threadIdx.x;
    const float* v  = h1root + g * DFEAT + kc;
    const float* Wb = Wl + (long)(512 + kc) * 512 + n;
    float acc = 0.f;
#pragma unroll 8
    for (int k = 0; k < 64; k++)
        acc += __ldg(v + k) * __ldg(Wb + (long)k * 512);
    atomicAdd(&rt2[g * DFEAT + n], acc);
}

// ---------------------------------------------------------------------------
// launch
// ---------------------------------------------------------------------------
extern "C" void kernel_launch(void* const* d_in, const int* in_sizes, int n_in,
                              void* d_out, int out_size)
{
    const float* features = (const float*)d_in[0];
    const int*   adjs     = (const int*)  d_in[1];
    const float* values   = (const float*)d_in[2];
    const int*   root_idx = (const int*)  d_in[3];
    const float* W1 = (const float*)d_in[6];
    const float* b1 = (const float*)d_in[7];
    const float* W2 = (const float*)d_in[8];
    const float* b2 = (const float*)d_in[9];
    const float* Wl = (const float*)d_in[10];
    const float* bl = (const float*)d_in[11];
    float* out = (float*)d_out;

    const int nE = in_sizes[2];

    float *S, *rt, *rt2, *h1root, *ew;
    int *cnt, *offs, *cursor, *ecol;
    __half *a16, *b16, *w1h, *w2h, *wlh;
    cudaGetSymbolAddress((void**)&S,      g_S);
    cudaGetSymbolAddress((void**)&rt,     g_rt);
    cudaGetSymbolAddress((void**)&rt2,    g_rt2);
    cudaGetSymbolAddress((void**)&h1root, g_h1root);
    cudaGetSymbolAddress((void**)&cnt,    g_cnt);
    cudaGetSymbolAddress((void**)&offs,   g_offs);
    cudaGetSymbolAddress((void**)&cursor, g_cursor);
    cudaGetSymbolAddress((void**)&ecol,   g_ecol);
    cudaGetSymbolAddress((void**)&ew,     g_ew);
    cudaGetSymbolAddress((void**)&a16, g_a16);
    cudaGetSymbolAddress((void**)&b16, g_b16);
    cudaGetSymbolAddress((void**)&w1h, g_w1h);
    cudaGetSymbolAddress((void**)&w2h, g_w2h);
    cudaGetSymbolAddress((void**)&wlh, g_wlh);

    const int* rows = adjs;
    const int* cols = adjs + nE;

    cudaFuncSetAttribute(gemm_fp16<3>, cudaFuncAttributeMaxDynamicSharedMemorySize, SMTOTAL);
    cudaFuncSetAttribute(gemm_fp16<4>, cudaFuncAttributeMaxDynamicSharedMemorySize, SMTOTAL);
    cudaFuncSetAttribute(gemm_fp16<2>, cudaFuncAttributeMaxDynamicSharedMemorySize, SMTOTAL);

    dim3 ggrid(DFEAT / BN2, MROWS / BM2);             // (4, 512)
    dim3 rtg(NGRAPH, 8);

    // #0: weights -> fp16 + cnt zero + rt/rt2 init
    split_w_zero_kernel<<<(3 * 512 * 512 + 255) / 256, 256>>>(
        W1, W2, Wl, bl, w1h, w2h, wlh, cnt, rt, rt2);
    // #1-3: CSR build
    hist_kernel<<<(nE + 255) / 256, 256>>>(rows, cnt, nE);
    scan_kernel<<<1, 1024>>>(cnt, offs, cursor);
    fill_csr_kernel<<<(nE + 255) / 256, 256>>>(rows, cols, values, cursor, ecol, ew, nE);
    // #4: PX = P @ X (fp32 src -> fp16) + S
    gather_f32_kernel<<<MROWS, 128>>>(features, offs, ecol, ew, a16, S);
    // #5: h1 = PX @ W1 + b1 (root-store, relu, quant) -> b16
    gemm_fp16<3><<<ggrid, 256, SMTOTAL>>>(a16, w1h, nullptr, b16,
                                          b1, nullptr, nullptr, root_idx, h1root);
    // #6-7: root terms
    root_term_kernel<<<rtg, 512>>>(features, root_idx, W2, rt);
    root_term2_kernel<<<rtg, 512>>>(h1root, Wl, rt2);
    // #8: Y = P @ relu(h1) (fp16) -> a16
    gather_f16_kernel<<<MROWS, 128>>>(b16, offs, ecol, ew, a16);
    // #9: h2 = Y @ W2a + b2 + S*rt[g] (relu, quant) -> b16
    gemm_fp16<4><<<ggrid, 256, SMTOTAL>>>(a16, w2h, nullptr, b16,
                                          b2, rt, S, nullptr, nullptr);
    // #10: out = leaky_relu(relu(h2) @ Wla + rt2[g])
    gemm_fp16<2><<<ggrid, 256, SMTOTAL>>>(b16, wlh, out, nullptr,
                                          nullptr, rt2, nullptr, nullptr, nullptr);
}

// round 17
// speedup vs baseline: 1.2243x; 1.0539x over previous
#include <cuda_runtime.h>
#include <cuda_fp16.h>
#include <cstdint>

#define MROWS   65536
#define DFEAT   512
#define NEDGES  65536
#define NGRAPH  16
#define GSHIFT  12          // rows per graph = 4096

// ---------------------------------------------------------------------------
// Scratch (__device__ globals; allocation-free)
// ---------------------------------------------------------------------------
__device__ float g_S[MROWS];
__device__ float g_rt[NGRAPH * DFEAT];
__device__ float g_rt2[NGRAPH * DFEAT];
__device__ float g_h1root[NGRAPH * DFEAT];
__device__ __half g_a16[(size_t)MROWS * DFEAT];     // activation buffer A
__device__ __half g_b16[(size_t)MROWS * DFEAT];     // activation buffer B
__device__ __half g_w1h[512 * 512];
__device__ __half g_w2h[512 * 512];
__device__ __half g_wlh[512 * 512];
// CSR
__device__ int   g_cnt[MROWS];
__device__ int   g_offs[MROWS + 1];
__device__ int   g_cursor[MROWS];
__device__ int   g_ecol[NEDGES];
__device__ float g_ew[NEDGES];

// ---------------------------------------------------------------------------
// PTX helpers
// ---------------------------------------------------------------------------
__device__ __forceinline__ uint32_t smem_u32(const void* p) {
    return (uint32_t)__cvta_generic_to_shared(p);
}
__device__ __forceinline__ void cp_async16(uint32_t dst, const void* src) {
    asm volatile("cp.async.cg.shared.global [%0], [%1], 16;" :: "r"(dst), "l"(src));
}
__device__ __forceinline__ void cp_commit() {
    asm volatile("cp.async.commit_group;");
}
template<int N>
__device__ __forceinline__ void cp_wait() {
    asm volatile("cp.async.wait_group %0;" :: "n"(N));
}
__device__ __forceinline__ void ldsm_x4(uint32_t& r0, uint32_t& r1,
                                        uint32_t& r2, uint32_t& r3, uint32_t a) {
    asm volatile("ldmatrix.sync.aligned.m8n8.x4.shared.b16 {%0,%1,%2,%3}, [%4];"
                 : "=r"(r0), "=r"(r1), "=r"(r2), "=r"(r3) : "r"(a));
}
__device__ __forceinline__ void mma16816(float* c, const uint32_t* a, const uint32_t* b) {
    asm volatile(
        "mma.sync.aligned.m16n8k16.row.col.f32.f16.f16.f32 "
        "{%0,%1,%2,%3}, {%4,%5,%6,%7}, {%8,%9}, {%0,%1,%2,%3};"
        : "+f"(c[0]), "+f"(c[1]), "+f"(c[2]), "+f"(c[3])
        : "r"(a[0]), "r"(a[1]), "r"(a[2]), "r"(a[3]), "r"(b[0]), "r"(b[1]));
}

// ---------------------------------------------------------------------------
// fp16 quantize-store helpers
// ---------------------------------------------------------------------------
__device__ __forceinline__ void q_store2(__half* p, float2 v) {
    *(__half2*)p = __floats2half2_rn(v.x, v.y);
}
__device__ __forceinline__ void q_store4(__half* p, float4 v) {
    q_store2(p,     make_float2(v.x, v.y));
    q_store2(p + 2, make_float2(v.z, v.w));
}

// ---------------------------------------------------------------------------
// fp16 1-term GEMM:  C = A16 @ B16^T   (fp32 accumulate)  -- R14 loop verbatim
// Warp tile 64x32, CTA 128x128, 256 thr (8 warps: 2M x 4N), 2 CTAs/SM.
// k32 chunks; each 128B smem row holds TWO k32 halves (16B-unit cols 0-3/4-7,
// disjoint under XOR swizzle) => built-in 2-stage pipeline, 2 x 16KB buffers.
// EPI=3: +bias(col); fp32 root-row store; relu; quant->Oh
// EPI=4: +bias(col)+S[row]*rt[g,col]; relu; quant->Oh
// EPI=2: +rt2[g,col]; leaky_relu; fp32 store -> C
// ---------------------------------------------------------------------------
#define BM2 128
#define BN2 128
#define SM_M (BM2 * 128)                  // 16 KB per matrix buffer
#define SMTOTAL (2 * SM_M + 1024)         // A, B (~33 KB)

template<int EPI>
__global__ void __launch_bounds__(256, 2)
gemm_fp16(const __half* __restrict__ A16, const __half* __restrict__ B16,
          float* __restrict__ C, __half* __restrict__ Oh,
          const float* __restrict__ bias, const float* __restrict__ rt,
          const float* __restrict__ S, const int* __restrict__ root_idx,
          float* __restrict__ h1root)
{
    constexpr int K = 512;
    constexpr int NCH = 16;               // k32 chunks
    extern __shared__ char dsm[];
    uint32_t sb = (smem_u32(dsm) + 1023) & ~1023u;

    const int tid  = threadIdx.x;
    const int lane = tid & 31;
    const int wid  = tid >> 5;            // 0..7
    const int wm   = wid & 1;             // 2 M-warps (64 rows each)
    const int wn   = wid >> 1;            // 4 N-warps (32 cols each)
    const long bm  = (long)blockIdx.y * BM2;
    const long bn  = (long)blockIdx.x * BN2;

    const uint32_t As = sb;
    const uint32_t Bs = sb + SM_M;

    float c[4][4][4];
#pragma unroll
    for (int i = 0; i < 4; i++)
#pragma unroll
        for (int j = 0; j < 4; j++)
#pragma unroll
            for (int q = 0; q < 4; q++) c[i][j][q] = 0.0f;

    const int amat  = lane >> 3;
    const int arow0 = wm * 64 + (amat & 1) * 8 + (lane & 7);
    const int ahalf = amat >> 1;
    const int bg    = lane >> 3;
    const int bhalf = bg & 1;
    const int bn0   = wn * 32 + ((bg >> 1) << 3) + (lane & 7);

    const __half* Ap = A16 + bm * K;
    const __half* Bp = B16 + bn * K;

    auto loads = [&](int ch) {
        int kk = ch << 5;                 // k offset (32 per chunk)
        int cb = (ch & 1) * 4;            // 16B-unit column base (half select)
#pragma unroll
        for (int i = 0; i < 2; i++) {
            int lin = tid * 2 + i;        // 0..511
            int r = lin >> 2;             // 0..127
            int u = lin & 3;              // 0..3
            uint32_t off = r * 128 + (((cb + u) ^ (r & 7)) << 4);
            long g = (long)r * K + kk + u * 8;
            cp_async16(As + off, Ap + g);
            cp_async16(Bs + off, Bp + g);
        }
    };

    loads(0); cp_commit();
    loads(1); cp_commit();

    for (int ch = 0; ch < NCH; ch++) {
        cp_wait<1>();
        __syncthreads();
        int cb = (ch & 1) * 4;
#pragma unroll
        for (int t = 0; t < 2; t++) {
            uint32_t a[4][4];
#pragma unroll
            for (int mi = 0; mi < 4; mi++) {
                int row = arow0 + mi * 16;
                uint32_t off = row * 128 + (((cb + 2 * t + ahalf) ^ (row & 7)) << 4);
                ldsm_x4(a[mi][0], a[mi][1], a[mi][2], a[mi][3], As + off);
            }
            uint32_t b[4][2];
#pragma unroll
            for (int j = 0; j < 2; j++) {
                int n = bn0 + j * 16;
                uint32_t off = n * 128 + (((cb + 2 * t + bhalf) ^ (n & 7)) << 4);
                ldsm_x4(b[2 * j][0], b[2 * j][1], b[2 * j + 1][0], b[2 * j + 1][1], Bs + off);
            }
#pragma unroll
            for (int mi = 0; mi < 4; mi++)
#pragma unroll
                for (int nj = 0; nj < 4; nj++)
                    mma16816(c[mi][nj], a[mi], b[nj]);
        }
        __syncthreads();                  // all warps done reading this half
        if (ch + 2 < NCH) loads(ch + 2);
        cp_commit();
    }

#pragma unroll
    for (int mi = 0; mi < 4; mi++) {
        long row = bm + wm * 64 + mi * 16 + (lane >> 2);
        int g = (int)(row >> GSHIFT);
#pragma unroll
        for (int nj = 0; nj < 4; nj++) {
            int col = (int)bn + wn * 32 + nj * 8 + 2 * (lane & 3);
            float2 v0 = {c[mi][nj][0], c[mi][nj][1]};   // row
            float2 v1 = {c[mi][nj][2], c[mi][nj][3]};   // row + 8

            if (EPI == 3) {
                float b0 = bias[col], b1v = bias[col + 1];
                v0.x += b0; v0.y += b1v; v1.x += b0; v1.y += b1v;
                int rr = root_idx[g];
                if ((long)rr == row) {
                    h1root[g * 512 + col] = v0.x; h1root[g * 512 + col + 1] = v0.y;
                }
                if ((long)rr == row + 8) {
                    h1root[g * 512 + col] = v1.x; h1root[g * 512 + col + 1] = v1.y;
                }
                v0.x = fmaxf(v0.x, 0.f); v0.y = fmaxf(v0.y, 0.f);
                v1.x = fmaxf(v1.x, 0.f); v1.y = fmaxf(v1.y, 0.f);
                q_store2(Oh + row * 512 + col, v0);
                q_store2(Oh + (row + 8) * 512 + col, v1);
            } else if (EPI == 4) {
                float s0 = S[row], s1 = S[row + 8];
                float r0 = rt[g * 512 + col], r1 = rt[g * 512 + col + 1];
                float b0 = bias[col], b1v = bias[col + 1];
                v0.x += b0 + s0 * r0; v0.y += b1v + s0 * r1;
                v1.x += b0 + s1 * r0; v1.y += b1v + s1 * r1;
                v0.x = fmaxf(v0.x, 0.f); v0.y = fmaxf(v0.y, 0.f);
                v1.x = fmaxf(v1.x, 0.f); v1.y = fmaxf(v1.y, 0.f);
                q_store2(Oh + row * 512 + col, v0);
                q_store2(Oh + (row + 8) * 512 + col, v1);
            } else {  // EPI == 2
                float b0 = rt[g * 512 + col], b1v = rt[g * 512 + col + 1];
                v0.x += b0; v0.y += b1v; v1.x += b0; v1.y += b1v;
                v0.x = (v0.x >= 0.f) ? v0.x : 0.01f * v0.x;
                v0.y = (v0.y >= 0.f) ? v0.y : 0.01f * v0.y;
                v1.x = (v1.x >= 0.f) ? v1.x : 0.01f * v1.x;
                v1.y = (v1.y >= 0.f) ? v1.y : 0.01f * v1.y;
                *(float2*)(C + row * 512 + col)       = v0;
                *(float2*)(C + (row + 8) * 512 + col) = v1;
            }
        }
    }
}

// ---------------------------------------------------------------------------
// prep: weights -> fp16 transposed, zero CSR histogram, init rt/rt2
// ---------------------------------------------------------------------------
__global__ void split_w_zero_kernel(const float* __restrict__ W1,
                                    const float* __restrict__ W2,
                                    const float* __restrict__ Wl,
                                    const float* __restrict__ bl,
                                    __half* __restrict__ w1h,
                                    __half* __restrict__ w2h,
                                    __half* __restrict__ wlh,
                                    int* __restrict__ cnt,
                                    float* __restrict__ rt, float* __restrict__ rt2)
{
    long idx = (long)blockIdx.x * blockDim.x + threadIdx.x;
    if (idx < MROWS) cnt[idx] = 0;
    if (idx < NGRAPH * DFEAT) { rt[idx] = 0.f; rt2[idx] = bl[idx & 511]; }
    if (idx >= 3 * 512 * 512) return;
    int which = (int)(idx >> 18);
    int loc   = (int)(idx & 0x3FFFF);
    int n = loc >> 9;
    int k = loc & 511;
    const float* W = (which == 0) ? W1 : (which == 1) ? W2 : Wl;
    __half* wh = (which == 0) ? w1h : (which == 1) ? w2h : wlh;
    wh[loc] = __float2half_rn(__ldg(&W[(long)k * 512 + n]));
}

// ---------------------------------------------------------------------------
// CSR build
// ---------------------------------------------------------------------------
__global__ void hist_kernel(const int* __restrict__ rows, int* __restrict__ cnt, int nE)
{
    int e = blockIdx.x * blockDim.x + threadIdx.x;
    if (e < nE) atomicAdd(&cnt[rows[e]], 1);
}
__global__ void __launch_bounds__(1024, 1)
scan_kernel(const int* __restrict__ cnt, int* __restrict__ offs, int* __restrict__ cursor)
{
    __shared__ int ts[1024];
    const int tid = threadIdx.x;
    const int base = tid * 64;
    int local = 0;
#pragma unroll 8
    for (int i = 0; i < 64; i++) local += cnt[base + i];
    int x = local;
    ts[tid] = x; __syncthreads();
    for (int s = 1; s < 1024; s <<= 1) {
        int v = (tid >= s) ? ts[tid - s] : 0;
        __syncthreads();
        x += v; ts[tid] = x; __syncthreads();
    }
    int run = x - local;
    for (int i = 0; i < 64; i++) {
        int cc = cnt[base + i];
        offs[base + i] = run;
        cursor[base + i] = run;
        run += cc;
    }
    if (tid == 1023) offs[MROWS] = run;
}
__global__ void fill_csr_kernel(const int* __restrict__ rows, const int* __restrict__ cols,
                                const float* __restrict__ vals, int* __restrict__ cursor,
                                int* __restrict__ ecol, float* __restrict__ ew, int nE)
{
    int e = blockIdx.x * blockDim.x + threadIdx.x;
    if (e >= nE) return;
    int p = atomicAdd(&cursor[rows[e]], 1);
    ecol[p] = cols[e];
    ew[p]   = vals[e];
}

// ---------------------------------------------------------------------------
// CSR gathers (one 128-thread block per destination row), 4-edge batching
// ---------------------------------------------------------------------------
__global__ void __launch_bounds__(128)
gather_f32_kernel(const float* __restrict__ src, const int* __restrict__ offs,
                  const int* __restrict__ ecol, const float* __restrict__ ew,
                  __half* __restrict__ oh, float* __restrict__ S)
{
    const int r = blockIdx.x;
    const int tid = threadIdx.x;
    const int beg = __ldg(&offs[r]), end = __ldg(&offs[r + 1]);
    float4 acc = make_float4(0.f, 0.f, 0.f, 0.f);
    float s = 0.f;
    int i = beg;
    for (; i + 4 <= end; i += 4) {
        int c0 = __ldg(&ecol[i]),   c1 = __ldg(&ecol[i+1]);
        int c2 = __ldg(&ecol[i+2]), c3 = __ldg(&ecol[i+3]);
        float w0 = __ldg(&ew[i]),   w1 = __ldg(&ew[i+1]);
        float w2 = __ldg(&ew[i+2]), w3 = __ldg(&ew[i+3]);
        float4 v0 = __ldg((const float4*)(src + (long)c0 * 512) + tid);
        float4 v1 = __ldg((const float4*)(src + (long)c1 * 512) + tid);
        float4 v2 = __ldg((const float4*)(src + (long)c2 * 512) + tid);
        float4 v3 = __ldg((const float4*)(src + (long)c3 * 512) + tid);
        acc.x += w0*v0.x + w1*v1.x + w2*v2.x + w3*v3.x;
        acc.y += w0*v0.y + w1*v1.y + w2*v2.y + w3*v3.y;
        acc.z += w0*v0.z + w1*v1.z + w2*v2.z + w3*v3.z;
        acc.w += w0*v0.w + w1*v1.w + w2*v2.w + w3*v3.w;
        s += w0 + w1 + w2 + w3;
    }
    for (; i < end; i++) {
        int cc = __ldg(&ecol[i]);
        float w = __ldg(&ew[i]);
        float4 v = __ldg((const float4*)(src + (long)cc * 512) + tid);
        acc.x += w * v.x; acc.y += w * v.y; acc.z += w * v.z; acc.w += w * v.w;
        s += w;
    }
    if (tid == 0) S[r] = s;
    q_store4(oh + (long)r * 512 + tid * 4, acc);
}

__device__ __forceinline__ float4 ld_f16row(const __half* sh, long row, int tid)
{
    const __half2* ph = (const __half2*)(sh + row * 512) + tid * 2;
    __half2 h0 = __ldg(ph), h1 = __ldg(ph + 1);
    float4 v;
    v.x = __half2float(h0.x); v.y = __half2float(h0.y);
    v.z = __half2float(h1.x); v.w = __half2float(h1.y);
    return v;
}

__global__ void __launch_bounds__(128)
gather_f16_kernel(const __half* __restrict__ sh,
                  const int* __restrict__ offs, const int* __restrict__ ecol,
                  const float* __restrict__ ew, __half* __restrict__ oh)
{
    const int r = blockIdx.x;
    const int tid = threadIdx.x;
    const int beg = __ldg(&offs[r]), end = __ldg(&offs[r + 1]);
    float4 acc = make_float4(0.f, 0.f, 0.f, 0.f);
    int i = beg;
    for (; i + 4 <= end; i += 4) {
        int c0 = __ldg(&ecol[i]),   c1 = __ldg(&ecol[i+1]);
        int c2 = __ldg(&ecol[i+2]), c3 = __ldg(&ecol[i+3]);
        float w0 = __ldg(&ew[i]),   w1 = __ldg(&ew[i+1]);
        float w2 = __ldg(&ew[i+2]), w3 = __ldg(&ew[i+3]);
        float4 v0 = ld_f16row(sh, c0, tid);
        float4 v1 = ld_f16row(sh, c1, tid);
        float4 v2 = ld_f16row(sh, c2, tid);
        float4 v3 = ld_f16row(sh, c3, tid);
        acc.x += w0*v0.x + w1*v1.x + w2*v2.x + w3*v3.x;
        acc.y += w0*v0.y + w1*v1.y + w2*v2.y + w3*v3.y;
        acc.z += w0*v0.z + w1*v1.z + w2*v2.z + w3*v3.z;
        acc.w += w0*v0.w + w1*v1.w + w2*v2.w + w3*v3.w;
    }
    for (; i < end; i++) {
        int cc = __ldg(&ecol[i]);
        float w = __ldg(&ew[i]);
        float4 v = ld_f16row(sh, cc, tid);
        acc.x += w * v.x; acc.y += w * v.y; acc.z += w * v.z; acc.w += w * v.w;
    }
    q_store4(oh + (long)r * 512 + tid * 4, acc);
}

// ---------------------------------------------------------------------------
// root terms (fp32 exact)
// ---------------------------------------------------------------------------
__global__ void __launch_bounds__(512)
root_term_kernel(const float* __restrict__ feat, const int* __restrict__ root_idx,
                 const float* __restrict__ W2, float* __restrict__ rt)
{
    int g  = blockIdx.x;
    int kc = blockIdx.y << 6;
    int n  = threadIdx.x;
    const float* v  = feat + (long)root_idx[g] * DFEAT + kc;
    const float* Wb = W2 + (long)(512 + kc) * 512 + n;
    float acc = 0.f;
#pragma unroll 8
    for (int k = 0; k < 64; k++)
        acc += fmaxf(__ldg(v + k), 0.f) * __ldg(Wb + (long)k * 512);
    atomicAdd(&rt[g * DFEAT + n], acc);
}
__global__ void __launch_bounds__(512)
root_term2_kernel(const float* __restrict__ h1root, const float* __restrict__ Wl,
                  float* __restrict__ rt2)
{
    int g  = blockIdx.x;
    int kc = blockIdx.y << 6;
    int n  = threadIdx.x;
    const float* v  = h1root + g * DFEAT + kc;
    const float* Wb = Wl + (long)(512 + kc) * 512 + n;
    float acc = 0.f;
#pragma unroll 8
    for (int k = 0; k < 64; k++)
        acc += __ldg(v + k) * __ldg(Wb + (long)k * 512);
    atomicAdd(&rt2[g * DFEAT + n], acc);
}

// ---------------------------------------------------------------------------
// launch
// ---------------------------------------------------------------------------
extern "C" void kernel_launch(void* const* d_in, const int* in_sizes, int n_in,
                              void* d_out, int out_size)
{
    const float* features = (const float*)d_in[0];
    const int*   adjs     = (const int*)  d_in[1];
    const float* values   = (const float*)d_in[2];
    const int*   root_idx = (const int*)  d_in[3];
    const float* W1 = (const float*)d_in[6];
    const float* b1 = (const float*)d_in[7];
    const float* W2 = (const float*)d_in[8];
    const float* b2 = (const float*)d_in[9];
    const float* Wl = (const float*)d_in[10];
    const float* bl = (const float*)d_in[11];
    float* out = (float*)d_out;

    const int nE = in_sizes[2];

    float *S, *rt, *rt2, *h1root, *ew;
    int *cnt, *offs, *cursor, *ecol;
    __half *a16, *b16, *w1h, *w2h, *wlh;
    cudaGetSymbolAddress((void**)&S,      g_S);
    cudaGetSymbolAddress((void**)&rt,     g_rt);
    cudaGetSymbolAddress((void**)&rt2,    g_rt2);
    cudaGetSymbolAddress((void**)&h1root, g_h1root);
    cudaGetSymbolAddress((void**)&cnt,    g_cnt);
    cudaGetSymbolAddress((void**)&offs,   g_offs);
    cudaGetSymbolAddress((void**)&cursor, g_cursor);
    cudaGetSymbolAddress((void**)&ecol,   g_ecol);
    cudaGetSymbolAddress((void**)&ew,     g_ew);
    cudaGetSymbolAddress((void**)&a16, g_a16);
    cudaGetSymbolAddress((void**)&b16, g_b16);
    cudaGetSymbolAddress((void**)&w1h, g_w1h);
    cudaGetSymbolAddress((void**)&w2h, g_w2h);
    cudaGetSymbolAddress((void**)&wlh, g_wlh);

    const int* rows = adjs;
    const int* cols = adjs + nE;

    cudaFuncSetAttribute(gemm_fp16<3>, cudaFuncAttributeMaxDynamicSharedMemorySize, SMTOTAL);
    cudaFuncSetAttribute(gemm_fp16<4>, cudaFuncAttributeMaxDynamicSharedMemorySize, SMTOTAL);
    cudaFuncSetAttribute(gemm_fp16<2>, cudaFuncAttributeMaxDynamicSharedMemorySize, SMTOTAL);

    dim3 ggrid(DFEAT / BN2, MROWS / BM2);             // (4, 512)
    dim3 rtg(NGRAPH, 8);

    // #0: weights -> fp16 + cnt zero + rt/rt2 init
    split_w_zero_kernel<<<(3 * 512 * 512 + 255) / 256, 256>>>(
        W1, W2, Wl, bl, w1h, w2h, wlh, cnt, rt, rt2);
    // #1-3: CSR build
    hist_kernel<<<(nE + 255) / 256, 256>>>(rows, cnt, nE);
    scan_kernel<<<1, 1024>>>(cnt, offs, cursor);
    fill_csr_kernel<<<(nE + 255) / 256, 256>>>(rows, cols, values, cursor, ecol, ew, nE);
    // #4: PX = P @ X (fp32 src -> fp16) + S
    gather_f32_kernel<<<MROWS, 128>>>(features, offs, ecol, ew, a16, S);
    // #5: h1 = PX @ W1 + b1 (root-store, relu, quant) -> b16
    gemm_fp16<3><<<ggrid, 256, SMTOTAL>>>(a16, w1h, nullptr, b16,
                                          b1, nullptr, nullptr, root_idx, h1root);
    // #6-7: root terms
    root_term_kernel<<<rtg, 512>>>(features, root_idx, W2, rt);
    root_term2_kernel<<<rtg, 512>>>(h1root, Wl, rt2);
    // #8: Y = P @ relu(h1) (fp16) -> a16
    gather_f16_kernel<<<MROWS, 128>>>(b16, offs, ecol, ew, a16);
    // #9: h2 = Y @ W2a + b2 + S*rt[g] (relu, quant) -> b16
    gemm_fp16<4><<<ggrid, 256, SMTOTAL>>>(a16, w2h, nullptr, b16,
                                          b2, rt, S, nullptr, nullptr);
    // #10: out = leaky_relu(relu(h2) @ Wla + rt2[g])
    gemm_fp16<2><<<ggrid, 256, SMTOTAL>>>(b16, wlh, out, nullptr,
                                          nullptr, rt2, nullptr, nullptr, nullptr);
}